// round 15
// baseline (speedup 1.0000x reference)
#include <cuda_runtime.h>
#include <cuda_fp16.h>

#define N_MAX   100000
#define FIN     512
#define HID     16
#define NC      7
#define H2      8
#define NB      256            // nodes per gemm block
#define TPB     128            // threads per gemm block (4 warps)
#define KC      16             // k floats per chunk
#define NCHUNK  (FIN / KC)     // 32
#define S       3              // pipeline stages
#define DEGB    192            // deg blocks (fit wave 1 with 391 gemm blocks)
#define SMEM_DYN ((S * (NB * 4 + 64)) * 16)

// -------- scratch (invariant: g_deg, g_agg1, g_agg2, g_ctr_deg zero at entry) --------
__device__ float    g_dinv[N_MAX];
__device__ float    g_deg [N_MAX];
__device__ unsigned g_xsh [N_MAX * 8];     // fp16x2: dinv * (x @ W1)
__device__ float    g_agg1[N_MAX * HID];
__device__ unsigned g_hsh [N_MAX * 4];     // fp16x2: dinv * (h1 @ W2)
__device__ float    g_agg2[N_MAX * H2];
__device__ int      g_ctr_deg;

__device__ __forceinline__ void red_add_v4(float* p, float4 v) {
    asm volatile("red.global.add.v4.f32 [%0], {%1,%2,%3,%4};"
                 :: "l"(p), "f"(v.x), "f"(v.y), "f"(v.z), "f"(v.w)
                 : "memory");
}
__device__ __forceinline__ void cp16(float4* dst_smem, const float4* src, bool pred) {
    unsigned d = (unsigned)__cvta_generic_to_shared(dst_smem);
    int sz = pred ? 16 : 0;
    asm volatile("cp.async.cg.shared.global [%0],[%1],16,%2;"
                 :: "r"(d), "l"(src), "r"(sz));
}
#define CP_COMMIT()  asm volatile("cp.async.commit_group;")
#define CP_WAIT1()   asm volatile("cp.async.wait_group 1;")

__device__ __forceinline__ unsigned h2pack(float a, float b) {
    __half2 h = __floats2half2_rn(a, b);
    return *(unsigned*)&h;
}
__device__ __forceinline__ float4 h4unpack(uint2 p) {
    float2 a = __half22float2(*(__half2*)&p.x);
    float2 b = __half22float2(*(__half2*)&p.y);
    return make_float4(a.x, a.y, b.x, b.y);
}
__device__ __forceinline__ void mma_tf32(float* c, const unsigned* a,
                                         const unsigned* b) {
    asm volatile(
        "mma.sync.aligned.m16n8k8.row.col.f32.tf32.tf32.f32 "
        "{%0,%1,%2,%3}, {%4,%5,%6,%7}, {%8,%9}, {%0,%1,%2,%3};"
        : "+f"(c[0]), "+f"(c[1]), "+f"(c[2]), "+f"(c[3])
        : "r"(a[0]), "r"(a[1]), "r"(a[2]), "r"(a[3]), "r"(b[0]), "r"(b[1]));
}
__device__ __forceinline__ unsigned tf32r(float f) {   // round-to-nearest tf32
    unsigned u;
    asm("cvt.rna.tf32.f32 %0,%1;" : "=r"(u) : "f"(f));
    return u;
}
__device__ __forceinline__ void tf32split(float f, unsigned& hi, unsigned& lo) {
    hi = tf32r(f);
    lo = tf32r(f - __uint_as_float(hi));
}
__device__ __forceinline__ void spin_until(int* ctr, int target) {
    while (atomicAdd(ctr, 0) < target) __nanosleep(128);
    __threadfence();
}

// ======== mega: blocks [0,GB) 2xTF32 gemm (+dinv/xsh epilogue),
//                blocks [GB,GB+DEGB) deg count ====
__global__ void __launch_bounds__(TPB)
k_mega(const float* __restrict__ x, const float* __restrict__ W1,
       const int* __restrict__ col, int n, int ne, int GB) {
    if (blockIdx.x >= GB) {
        int t0 = (blockIdx.x - GB) * TPB + threadIdx.x;
        int stride = DEGB * TPB;
        for (int e = t0; e < ne; e += stride)
            atomicAdd(&g_deg[__ldg(&col[e])], 1.0f);
        __threadfence();
        __syncthreads();
        if (threadIdx.x == 0) atomicAdd(&g_ctr_deg, 1);
        return;
    }

    extern __shared__ float4 smem[];
    float4* sX4 = smem;                 // S * NB*4
    float4* sW4 = smem + S * NB * 4;    // S * 64

    const int tid  = threadIdx.x;
    const int base = blockIdx.x * NB;
    const int warp = tid >> 5;
    const int lane = tid & 31;
    const int lg   = lane >> 2;         // group 0..7
    const int lw   = lane & 3;          // thread-in-group 0..3
    const int sr   = tid >> 2;          // staging base row
    const int c4   = tid & 3;           // staging float4 col

    float Cr[8][4];                     // [m-tile*2 + n-tile][4]
#pragma unroll
    for (int i = 0; i < 8; i++)
#pragma unroll
        for (int j = 0; j < 4; j++) Cr[i][j] = 0.f;

#define ISSUE(cc, ss)                                                        \
    do {                                                                     \
        float4* dx = &sX4[(ss) * NB * 4];                                    \
        _Pragma("unroll")                                                    \
        for (int i = 0; i < 8; i++) {                                        \
            int r  = sr + i * 32;                                            \
            int gn = base + r;                                               \
            cp16(&dx[r * 4 + (c4 ^ ((r >> 1) & 3))],                         \
                 (const float4*)(x + (size_t)gn * FIN + (cc) * KC) + c4,     \
                 gn < n);                                                    \
        }                                                                    \
        if (tid < 64)                                                        \
            cp16(&sW4[(ss) * 64 + tid],                                      \
                 (const float4*)W1 + (cc) * 64 + tid, true);                 \
        CP_COMMIT();                                                         \
    } while (0)

    ISSUE(0, 0);
    ISSUE(1, 1);

    for (int c = 0; c < NCHUNK; c++) {
        CP_WAIT1();
        __syncthreads();

        if (c + 2 < NCHUNK) { int s2 = (c + 2) % S; ISSUE(c + 2, s2); }
        else CP_COMMIT();

        const int s = c % S;
        const float* bxf = (const float*)(&sX4[s * NB * 4]);
        const float* sWf = (const float*)(&sW4[s * 64]);

        // B fragments, hi/lo split (exact): [ks][nt][2]
        unsigned Bh[2][2][2], Bl[2][2][2];
#pragma unroll
        for (int ks = 0; ks < 2; ks++)
#pragma unroll
            for (int nt = 0; nt < 2; nt++) {
                float w0 = sWf[(ks * 8 + lw) * HID + nt * 8 + lg];
                float w1 = sWf[(ks * 8 + 4 + lw) * HID + nt * 8 + lg];
                tf32split(w0, Bh[ks][nt][0], Bl[ks][nt][0]);
                tf32split(w1, Bh[ks][nt][1], Bl[ks][nt][1]);
            }

#pragma unroll
        for (int t = 0; t < 4; t++) {
            const int r  = warp * 64 + t * 16 + lg;    // node row in tile
            const int swr = (r >> 1) & 3;
#pragma unroll
            for (int ks = 0; ks < 2; ks++) {
                const int j0 = ks * 2;                 // float4 col of k0
                unsigned A[4];
                A[0] = tf32r(bxf[(r * 4       + (j0 ^ swr)) * 4 + lw]);
                A[1] = tf32r(bxf[((r + 8) * 4 + (j0 ^ swr)) * 4 + lw]);
                A[2] = tf32r(bxf[(r * 4       + ((j0 + 1) ^ swr)) * 4 + lw]);
                A[3] = tf32r(bxf[((r + 8) * 4 + ((j0 + 1) ^ swr)) * 4 + lw]);
#pragma unroll
                for (int nt = 0; nt < 2; nt++) {
                    float* cc = Cr[t * 2 + nt];
                    mma_tf32(cc, A, Bl[ks][nt]);   // small term first
                    mma_tf32(cc, A, Bh[ks][nt]);
                }
            }
        }
    }
#undef ISSUE

    // ---- epilogue: wait for deg histogram (long since done), then
    //      dinv = rsqrt(deg+1) and xsh = fp16(dinv * C) straight from regs ----
    if (tid == 0) spin_until(&g_ctr_deg, DEGB);
    __syncthreads();

#pragma unroll
    for (int t = 0; t < 4; t++) {
        int gr = base + warp * 64 + t * 16 + lg;
        float d0 = 0.f, d1 = 0.f;
        if (gr < n)     d0 = rsqrtf(g_deg[gr] + 1.0f);
        if (gr + 8 < n) d1 = rsqrtf(g_deg[gr + 8] + 1.0f);
        if (lw == 0) {
            if (gr < n)     g_dinv[gr]     = d0;
            if (gr + 8 < n) g_dinv[gr + 8] = d1;
        }
#pragma unroll
        for (int nt = 0; nt < 2; nt++) {
            const float* cc = Cr[t * 2 + nt];
            if (gr < n)
                g_xsh[(size_t)gr * 8 + nt * 4 + lw] =
                    h2pack(d0 * cc[0], d0 * cc[1]);
            if (gr + 8 < n)
                g_xsh[(size_t)(gr + 8) * 8 + nt * 4 + lw] =
                    h2pack(d1 * cc[2], d1 * cc[3]);
        }
    }
}

// ---- layer-1 aggregation: fp16 gather, fp32 red; 4 lanes / 4 edges ----
__global__ void k_agg1(const int* __restrict__ row,
                       const int* __restrict__ col, int ne) {
    int t = blockIdx.x * blockDim.x + threadIdx.x;
    int g = t >> 2, q = t & 3;
    int e0 = g * 4;
    if (e0 >= ne) return;
    if (e0 + 4 <= ne) {
        int r[4], c[4];
#pragma unroll
        for (int j = 0; j < 4; j++) {
            r[j] = __ldg(&row[e0 + j]);
            c[j] = __ldg(&col[e0 + j]);
        }
        uint2 p[4];
#pragma unroll
        for (int j = 0; j < 4; j++)
            p[j] = *(const uint2*)(&g_xsh[(size_t)r[j] * 8 + q * 2]);
#pragma unroll
        for (int j = 0; j < 4; j++)
            red_add_v4(&g_agg1[(size_t)c[j] * HID + q * 4], h4unpack(p[j]));
    } else {
        for (int e = e0; e < ne; e++) {
            int r = __ldg(&row[e]);
            int c = __ldg(&col[e]);
            uint2 p = *(const uint2*)(&g_xsh[(size_t)r * 8 + q * 2]);
            red_add_v4(&g_agg1[(size_t)c * HID + q * 4], h4unpack(p));
        }
    }
}

// ---- h1 = relu(dinv*(agg1 + xsh) + b1); hsh = fp16(dinv*(h1 @ W2));
//      restores agg1 to zero ----
__global__ void k_h1(const float* __restrict__ b1,
                     const float* __restrict__ W2, int n) {
    __shared__ float sW2[HID * NC];
    __shared__ float sb1[HID];
    if (threadIdx.x < HID * NC) sW2[threadIdx.x] = W2[threadIdx.x];
    if (threadIdx.x < HID)      sb1[threadIdx.x] = b1[threadIdx.x];
    __syncthreads();

    int i = blockIdx.x * blockDim.x + threadIdx.x;
    if (i >= n) return;

    float d = g_dinv[i];
    const uint4* xq = (const uint4*)(&g_xsh[(size_t)i * 8]);
    uint4 x0 = xq[0], x1 = xq[1];
    float xsv[HID];
    { float4 a = h4unpack(make_uint2(x0.x, x0.y));
      float4 b = h4unpack(make_uint2(x0.z, x0.w));
      float4 c = h4unpack(make_uint2(x1.x, x1.y));
      float4 e = h4unpack(make_uint2(x1.z, x1.w));
      xsv[0]=a.x;  xsv[1]=a.y;  xsv[2]=a.z;   xsv[3]=a.w;
      xsv[4]=b.x;  xsv[5]=b.y;  xsv[6]=b.z;   xsv[7]=b.w;
      xsv[8]=c.x;  xsv[9]=c.y;  xsv[10]=c.z;  xsv[11]=c.w;
      xsv[12]=e.x; xsv[13]=e.y; xsv[14]=e.z;  xsv[15]=e.w; }

    float4* ag = (float4*)(&g_agg1[(size_t)i * HID]);
    float h[HID];
#pragma unroll
    for (int j4 = 0; j4 < 4; j4++) {
        float4 a = ag[j4];
        float av[4] = {a.x, a.y, a.z, a.w};
#pragma unroll
        for (int u = 0; u < 4; u++) {
            int j = j4 * 4 + u;
            float v = d * (av[u] + xsv[j]) + sb1[j];
            h[j] = v > 0.f ? v : 0.f;
        }
        ag[j4] = make_float4(0.f, 0.f, 0.f, 0.f);   // restore zero
    }

    float y[H2];
#pragma unroll
    for (int j = 0; j < H2; j++) y[j] = 0.f;
#pragma unroll
    for (int k = 0; k < HID; k++) {
        float hk = h[k];
#pragma unroll
        for (int j = 0; j < NC; j++) y[j] += hk * sW2[k * NC + j];
    }
    uint4* o = (uint4*)(&g_hsh[(size_t)i * 4]);
    *o = make_uint4(h2pack(d * y[0], d * y[1]), h2pack(d * y[2], d * y[3]),
                    h2pack(d * y[4], d * y[5]), h2pack(d * y[6], 0.f));
}

// ---- layer-2 aggregation: fp16 gather; 2 lanes / 4 edges ----
__global__ void k_agg2(const int* __restrict__ row,
                       const int* __restrict__ col, int ne) {
    int t = blockIdx.x * blockDim.x + threadIdx.x;
    int g = t >> 1, q = t & 1;
    int e0 = g * 4;
    if (e0 >= ne) return;
    if (e0 + 4 <= ne) {
        int r[4], c[4];
#pragma unroll
        for (int j = 0; j < 4; j++) {
            r[j] = __ldg(&row[e0 + j]);
            c[j] = __ldg(&col[e0 + j]);
        }
        uint2 p[4];
#pragma unroll
        for (int j = 0; j < 4; j++)
            p[j] = *(const uint2*)(&g_hsh[(size_t)r[j] * 4 + q * 2]);
#pragma unroll
        for (int j = 0; j < 4; j++)
            red_add_v4(&g_agg2[(size_t)c[j] * H2 + q * 4], h4unpack(p[j]));
    } else {
        for (int e = e0; e < ne; e++) {
            int r = __ldg(&row[e]);
            int c = __ldg(&col[e]);
            uint2 p = *(const uint2*)(&g_hsh[(size_t)r * 4 + q * 2]);
            red_add_v4(&g_agg2[(size_t)c * H2 + q * 4], h4unpack(p));
        }
    }
}

// ---- out = dinv*(agg2 + hsh) + b2; restores agg2, deg, counter ----
__global__ void k_out(float* __restrict__ out, const float* __restrict__ b2, int n) {
    int i = blockIdx.x * blockDim.x + threadIdx.x;
    if (i >= n) return;
    float d = g_dinv[i];
    uint4 hq = *(const uint4*)(&g_hsh[(size_t)i * 4]);
    float4 ha = h4unpack(make_uint2(hq.x, hq.y));
    float4 hb = h4unpack(make_uint2(hq.z, hq.w));
    float hs[8] = {ha.x, ha.y, ha.z, ha.w, hb.x, hb.y, hb.z, hb.w};

    float4* ag = (float4*)(&g_agg2[(size_t)i * H2]);
    float4 a0 = ag[0], a1 = ag[1];
    float av[8] = {a0.x, a0.y, a0.z, a0.w, a1.x, a1.y, a1.z, a1.w};
#pragma unroll
    for (int j = 0; j < NC; j++)
        out[(size_t)i * NC + j] = d * (av[j] + hs[j]) + __ldg(&b2[j]);

    ag[0] = make_float4(0.f, 0.f, 0.f, 0.f);    // restore zero
    ag[1] = make_float4(0.f, 0.f, 0.f, 0.f);
    g_deg[i] = 0.f;
    if (i == 0) g_ctr_deg = 0;
}

extern "C" void kernel_launch(void* const* d_in, const int* in_sizes, int n_in,
                              void* d_out, int out_size) {
    const float* x  = (const float*)d_in[0];
    const int*   ei = (const int*)  d_in[1];
    const float* W1 = (const float*)d_in[2];
    const float* b1 = (const float*)d_in[3];
    const float* W2 = (const float*)d_in[4];
    const float* b2 = (const float*)d_in[5];

    int n  = in_sizes[0] / FIN;
    int ne = in_sizes[1] / 2;
    const int* row = ei;
    const int* col = ei + ne;
    int GB = (n + NB - 1) / NB;

    cudaFuncSetAttribute(k_mega, cudaFuncAttributeMaxDynamicSharedMemorySize, SMEM_DYN);

    k_mega<<<GB + DEGB, TPB, SMEM_DYN>>>(x, W1, col, n, ne, GB);
    k_agg1<<<(ne + 255) / 256, 256>>>(row, col, ne);
    k_h1  <<<(n + 255) / 256, 256>>>(b1, W2, n);
    k_agg2<<<((ne / 2) + 255) / 256, 256>>>(row, col, ne);
    k_out <<<(n + 255) / 256, 256>>>((float*)d_out, b2, n);
}

// round 16
// speedup vs baseline: 1.2941x; 1.2941x over previous
#include <cuda_runtime.h>
#include <cuda_fp16.h>

#define N_MAX   100000
#define FIN     512
#define HID     16
#define NC      7
#define H2      8
#define NB      256            // nodes per gemm block
#define TPB     128            // threads per gemm block (4 warps)
#define KC      16             // k floats per chunk
#define NCHUNK  (FIN / KC)     // 32
#define S       3              // pipeline stages
#define DEGB    192            // deg blocks (fit wave 1 with 391 gemm blocks)
#define SMEM_DYN ((S * (NB * 4 + 64)) * 16)

// -------- scratch (invariant: g_deg, g_agg1, g_agg2 zero at entry) --------
__device__ float    g_dinv[N_MAX];
__device__ float    g_deg [N_MAX];
__device__ float    g_xs  [N_MAX * HID];   // x @ W1 (fp32, pre-dinv)
__device__ unsigned g_xsh [N_MAX * 8];     // fp16x2: dinv * (x @ W1)
__device__ float    g_agg1[N_MAX * HID];
__device__ unsigned g_hsh [N_MAX * 4];     // fp16x2: dinv * (h1 @ W2)
__device__ float    g_agg2[N_MAX * H2];

__device__ __forceinline__ void red_add_v4(float* p, float4 v) {
    asm volatile("red.global.add.v4.f32 [%0], {%1,%2,%3,%4};"
                 :: "l"(p), "f"(v.x), "f"(v.y), "f"(v.z), "f"(v.w)
                 : "memory");
}
__device__ __forceinline__ void cp16(float4* dst_smem, const float4* src, bool pred) {
    unsigned d = (unsigned)__cvta_generic_to_shared(dst_smem);
    int sz = pred ? 16 : 0;
    asm volatile("cp.async.cg.shared.global [%0],[%1],16,%2;"
                 :: "r"(d), "l"(src), "r"(sz));
}
#define CP_COMMIT()  asm volatile("cp.async.commit_group;")
#define CP_WAIT1()   asm volatile("cp.async.wait_group 1;")

__device__ __forceinline__ unsigned h2pack(float a, float b) {
    __half2 h = __floats2half2_rn(a, b);
    return *(unsigned*)&h;
}
__device__ __forceinline__ float4 h4unpack(uint2 p) {
    float2 a = __half22float2(*(__half2*)&p.x);
    float2 b = __half22float2(*(__half2*)&p.y);
    return make_float4(a.x, a.y, b.x, b.y);
}
__device__ __forceinline__ void mma_tf32(float* c, const unsigned* a,
                                         const unsigned* b) {
    asm volatile(
        "mma.sync.aligned.m16n8k8.row.col.f32.tf32.tf32.f32 "
        "{%0,%1,%2,%3}, {%4,%5,%6,%7}, {%8,%9}, {%0,%1,%2,%3};"
        : "+f"(c[0]), "+f"(c[1]), "+f"(c[2]), "+f"(c[3])
        : "r"(a[0]), "r"(a[1]), "r"(a[2]), "r"(a[3]), "r"(b[0]), "r"(b[1]));
}
__device__ __forceinline__ unsigned tf32r(float f) {   // round-to-nearest tf32
    unsigned u;
    asm("cvt.rna.tf32.f32 %0,%1;" : "=r"(u) : "f"(f));
    return u;
}
__device__ __forceinline__ void tf32split(float f, unsigned& hi, unsigned& lo) {
    hi = tf32r(f);
    lo = tf32r(f - __uint_as_float(hi));
}

// ======== mega: blocks [0,GB) 2xTF32 gemm, blocks [GB,GB+DEGB) deg count ====
__global__ void __launch_bounds__(TPB)
k_mega(const float* __restrict__ x, const float* __restrict__ W1,
       const int* __restrict__ col, int n, int ne, int GB) {
    if (blockIdx.x >= GB) {
        int t0 = (blockIdx.x - GB) * TPB + threadIdx.x;
        int stride = DEGB * TPB;
        for (int e = t0; e < ne; e += stride)
            atomicAdd(&g_deg[__ldg(&col[e])], 1.0f);
        return;
    }

    extern __shared__ float4 smem[];
    float4* sX4 = smem;                 // S * NB*4
    float4* sW4 = smem + S * NB * 4;    // S * 64

    const int tid  = threadIdx.x;
    const int base = blockIdx.x * NB;
    const int warp = tid >> 5;
    const int lane = tid & 31;
    const int lg   = lane >> 2;         // group 0..7
    const int lw   = lane & 3;          // thread-in-group 0..3
    const int sr   = tid >> 2;          // staging base row
    const int c4   = tid & 3;           // staging float4 col

    float Cr[8][4];                     // [m-tile*2 + n-tile][4]
#pragma unroll
    for (int i = 0; i < 8; i++)
#pragma unroll
        for (int j = 0; j < 4; j++) Cr[i][j] = 0.f;

#define ISSUE(cc, ss)                                                        \
    do {                                                                     \
        float4* dx = &sX4[(ss) * NB * 4];                                    \
        _Pragma("unroll")                                                    \
        for (int i = 0; i < 8; i++) {                                        \
            int r  = sr + i * 32;                                            \
            int gn = base + r;                                               \
            cp16(&dx[r * 4 + (c4 ^ ((r >> 1) & 3))],                         \
                 (const float4*)(x + (size_t)gn * FIN + (cc) * KC) + c4,     \
                 gn < n);                                                    \
        }                                                                    \
        if (tid < 64)                                                        \
            cp16(&sW4[(ss) * 64 + tid],                                      \
                 (const float4*)W1 + (cc) * 64 + tid, true);                 \
        CP_COMMIT();                                                         \
    } while (0)

    ISSUE(0, 0);
    ISSUE(1, 1);

    for (int c = 0; c < NCHUNK; c++) {
        CP_WAIT1();
        __syncthreads();

        if (c + 2 < NCHUNK) { int s2 = (c + 2) % S; ISSUE(c + 2, s2); }
        else CP_COMMIT();

        const int s = c % S;
        const float* bxf = (const float*)(&sX4[s * NB * 4]);
        const float* sWf = (const float*)(&sW4[s * 64]);

        // B fragments, hi/lo split (exact): [ks][nt][2]
        unsigned Bh[2][2][2], Bl[2][2][2];
#pragma unroll
        for (int ks = 0; ks < 2; ks++)
#pragma unroll
            for (int nt = 0; nt < 2; nt++) {
                float w0 = sWf[(ks * 8 + lw) * HID + nt * 8 + lg];
                float w1 = sWf[(ks * 8 + 4 + lw) * HID + nt * 8 + lg];
                tf32split(w0, Bh[ks][nt][0], Bl[ks][nt][0]);
                tf32split(w1, Bh[ks][nt][1], Bl[ks][nt][1]);
            }

#pragma unroll
        for (int t = 0; t < 4; t++) {
            const int r  = warp * 64 + t * 16 + lg;    // node row in tile
            const int swr = (r >> 1) & 3;
#pragma unroll
            for (int ks = 0; ks < 2; ks++) {
                const int j0 = ks * 2;                 // float4 col of k0
                unsigned A[4];
                A[0] = tf32r(bxf[(r * 4       + (j0 ^ swr)) * 4 + lw]);
                A[1] = tf32r(bxf[((r + 8) * 4 + (j0 ^ swr)) * 4 + lw]);
                A[2] = tf32r(bxf[(r * 4       + ((j0 + 1) ^ swr)) * 4 + lw]);
                A[3] = tf32r(bxf[((r + 8) * 4 + ((j0 + 1) ^ swr)) * 4 + lw]);
#pragma unroll
                for (int nt = 0; nt < 2; nt++) {
                    float* cc = Cr[t * 2 + nt];
                    mma_tf32(cc, A, Bl[ks][nt]);   // small term first
                    mma_tf32(cc, A, Bh[ks][nt]);
                }
            }
        }
    }
#undef ISSUE

    // ---- epilogue: write C fragments to g_xs ----
#pragma unroll
    for (int t = 0; t < 4; t++) {
        int gr = base + warp * 64 + t * 16 + lg;
#pragma unroll
        for (int nt = 0; nt < 2; nt++) {
            const float* cc = Cr[t * 2 + nt];
            if (gr < n)
                *(float2*)(&g_xs[(size_t)gr * HID + nt * 8 + lw * 2]) =
                    make_float2(cc[0], cc[1]);
            if (gr + 8 < n)
                *(float2*)(&g_xs[(size_t)(gr + 8) * HID + nt * 8 + lw * 2]) =
                    make_float2(cc[2], cc[3]);
        }
    }
}

// ---- finish: dinv = rsqrt(deg+1); xsh = fp16(dinv * xs) ----
__global__ void k_finish(int n) {
    int i = blockIdx.x * blockDim.x + threadIdx.x;
    if (i >= n) return;
    float d = rsqrtf(g_deg[i] + 1.0f);
    g_dinv[i] = d;
    const float4* p = (const float4*)(&g_xs[(size_t)i * HID]);
    uint4 o[2];
#pragma unroll
    for (int j = 0; j < 2; j++) {
        float4 a = p[j * 2], b = p[j * 2 + 1];
        o[j] = make_uint4(h2pack(d * a.x, d * a.y), h2pack(d * a.z, d * a.w),
                          h2pack(d * b.x, d * b.y), h2pack(d * b.z, d * b.w));
    }
    uint4* q = (uint4*)(&g_xsh[(size_t)i * 8]);
    q[0] = o[0]; q[1] = o[1];
}

// ---- layer-1 aggregation: fp16 gather, fp32 red; 4 lanes / 8 edges ----
__global__ void k_agg1(const int* __restrict__ row,
                       const int* __restrict__ col, int ne) {
    int t = blockIdx.x * blockDim.x + threadIdx.x;
    int g = t >> 2, q = t & 3;
    int e0 = g * 8;
    if (e0 >= ne) return;
    if (e0 + 8 <= ne) {
        int r[8], c[8];
#pragma unroll
        for (int j = 0; j < 8; j++) {
            r[j] = __ldg(&row[e0 + j]);
            c[j] = __ldg(&col[e0 + j]);
        }
        uint2 p[8];
#pragma unroll
        for (int j = 0; j < 8; j++)
            p[j] = *(const uint2*)(&g_xsh[(size_t)r[j] * 8 + q * 2]);
#pragma unroll
        for (int j = 0; j < 8; j++)
            red_add_v4(&g_agg1[(size_t)c[j] * HID + q * 4], h4unpack(p[j]));
    } else {
        for (int e = e0; e < ne; e++) {
            int r = __ldg(&row[e]);
            int c = __ldg(&col[e]);
            uint2 p = *(const uint2*)(&g_xsh[(size_t)r * 8 + q * 2]);
            red_add_v4(&g_agg1[(size_t)c * HID + q * 4], h4unpack(p));
        }
    }
}

// ---- h1 = relu(dinv*(agg1 + xsh) + b1); hsh = fp16(dinv*(h1 @ W2));
//      restores agg1 to zero ----
__global__ void k_h1(const float* __restrict__ b1,
                     const float* __restrict__ W2, int n) {
    __shared__ float sW2[HID * NC];
    __shared__ float sb1[HID];
    if (threadIdx.x < HID * NC) sW2[threadIdx.x] = W2[threadIdx.x];
    if (threadIdx.x < HID)      sb1[threadIdx.x] = b1[threadIdx.x];
    __syncthreads();

    int i = blockIdx.x * blockDim.x + threadIdx.x;
    if (i >= n) return;

    float d = g_dinv[i];
    const uint4* xq = (const uint4*)(&g_xsh[(size_t)i * 8]);
    uint4 x0 = xq[0], x1 = xq[1];
    float xsv[HID];
    { float4 a = h4unpack(make_uint2(x0.x, x0.y));
      float4 b = h4unpack(make_uint2(x0.z, x0.w));
      float4 c = h4unpack(make_uint2(x1.x, x1.y));
      float4 e = h4unpack(make_uint2(x1.z, x1.w));
      xsv[0]=a.x;  xsv[1]=a.y;  xsv[2]=a.z;   xsv[3]=a.w;
      xsv[4]=b.x;  xsv[5]=b.y;  xsv[6]=b.z;   xsv[7]=b.w;
      xsv[8]=c.x;  xsv[9]=c.y;  xsv[10]=c.z;  xsv[11]=c.w;
      xsv[12]=e.x; xsv[13]=e.y; xsv[14]=e.z;  xsv[15]=e.w; }

    float4* ag = (float4*)(&g_agg1[(size_t)i * HID]);
    float h[HID];
#pragma unroll
    for (int j4 = 0; j4 < 4; j4++) {
        float4 a = ag[j4];
        float av[4] = {a.x, a.y, a.z, a.w};
#pragma unroll
        for (int u = 0; u < 4; u++) {
            int j = j4 * 4 + u;
            float v = d * (av[u] + xsv[j]) + sb1[j];
            h[j] = v > 0.f ? v : 0.f;
        }
        ag[j4] = make_float4(0.f, 0.f, 0.f, 0.f);   // restore zero
    }

    float y[H2];
#pragma unroll
    for (int j = 0; j < H2; j++) y[j] = 0.f;
#pragma unroll
    for (int k = 0; k < HID; k++) {
        float hk = h[k];
#pragma unroll
        for (int j = 0; j < NC; j++) y[j] += hk * sW2[k * NC + j];
    }
    uint4* o = (uint4*)(&g_hsh[(size_t)i * 4]);
    *o = make_uint4(h2pack(d * y[0], d * y[1]), h2pack(d * y[2], d * y[3]),
                    h2pack(d * y[4], d * y[5]), h2pack(d * y[6], 0.f));
}

// ---- layer-2 aggregation: fp16 gather; 2 lanes / 8 edges ----
__global__ void k_agg2(const int* __restrict__ row,
                       const int* __restrict__ col, int ne) {
    int t = blockIdx.x * blockDim.x + threadIdx.x;
    int g = t >> 1, q = t & 1;
    int e0 = g * 8;
    if (e0 >= ne) return;
    if (e0 + 8 <= ne) {
        int r[8], c[8];
#pragma unroll
        for (int j = 0; j < 8; j++) {
            r[j] = __ldg(&row[e0 + j]);
            c[j] = __ldg(&col[e0 + j]);
        }
        uint2 p[8];
#pragma unroll
        for (int j = 0; j < 8; j++)
            p[j] = *(const uint2*)(&g_hsh[(size_t)r[j] * 4 + q * 2]);
#pragma unroll
        for (int j = 0; j < 8; j++)
            red_add_v4(&g_agg2[(size_t)c[j] * H2 + q * 4], h4unpack(p[j]));
    } else {
        for (int e = e0; e < ne; e++) {
            int r = __ldg(&row[e]);
            int c = __ldg(&col[e]);
            uint2 p = *(const uint2*)(&g_hsh[(size_t)r * 4 + q * 2]);
            red_add_v4(&g_agg2[(size_t)c * H2 + q * 4], h4unpack(p));
        }
    }
}

// ---- out = dinv*(agg2 + hsh) + b2; restores agg2 and deg to zero ----
__global__ void k_out(float* __restrict__ out, const float* __restrict__ b2, int n) {
    int i = blockIdx.x * blockDim.x + threadIdx.x;
    if (i >= n) return;
    float d = g_dinv[i];
    uint4 hq = *(const uint4*)(&g_hsh[(size_t)i * 4]);
    float4 ha = h4unpack(make_uint2(hq.x, hq.y));
    float4 hb = h4unpack(make_uint2(hq.z, hq.w));
    float hs[8] = {ha.x, ha.y, ha.z, ha.w, hb.x, hb.y, hb.z, hb.w};

    float4* ag = (float4*)(&g_agg2[(size_t)i * H2]);
    float4 a0 = ag[0], a1 = ag[1];
    float av[8] = {a0.x, a0.y, a0.z, a0.w, a1.x, a1.y, a1.z, a1.w};
#pragma unroll
    for (int j = 0; j < NC; j++)
        out[(size_t)i * NC + j] = d * (av[j] + hs[j]) + __ldg(&b2[j]);

    ag[0] = make_float4(0.f, 0.f, 0.f, 0.f);    // restore zero
    ag[1] = make_float4(0.f, 0.f, 0.f, 0.f);
    g_deg[i] = 0.f;
}

extern "C" void kernel_launch(void* const* d_in, const int* in_sizes, int n_in,
                              void* d_out, int out_size) {
    const float* x  = (const float*)d_in[0];
    const int*   ei = (const int*)  d_in[1];
    const float* W1 = (const float*)d_in[2];
    const float* b1 = (const float*)d_in[3];
    const float* W2 = (const float*)d_in[4];
    const float* b2 = (const float*)d_in[5];

    int n  = in_sizes[0] / FIN;
    int ne = in_sizes[1] / 2;
    const int* row = ei;
    const int* col = ei + ne;
    int GB = (n + NB - 1) / NB;

    cudaFuncSetAttribute(k_mega, cudaFuncAttributeMaxDynamicSharedMemorySize, SMEM_DYN);

    k_mega  <<<GB + DEGB, TPB, SMEM_DYN>>>(x, W1, col, n, ne, GB);
    k_finish<<<(n + 255) / 256, 256>>>(n);
    k_agg1  <<<((ne / 2) + 255) / 256, 256>>>(row, col, ne);
    k_h1    <<<(n + 255) / 256, 256>>>(b1, W2, n);
    k_agg2  <<<((ne / 4) + 255) / 256, 256>>>(row, col, ne);
    k_out   <<<(n + 255) / 256, 256>>>((float*)d_out, b2, n);
}